// round 16
// baseline (speedup 1.0000x reference)
#include <cuda_runtime.h>
#include <cuda_bf16.h>
#include <math.h>
#include <stdint.h>

#define E      2048
#define TT     1024
#define BATCH  2
#define MROWS  (BATCH * TT)   // 2048
#define NKV    8
#define NQ     32
#define HD     64
#define KVW    (NKV * HD)     // 512

// ---------------- scratch (device globals; no allocations allowed) -------
__device__ float g_q[MROWS * E];
__device__ float g_k[MROWS * KVW];
__device__ float g_v[MROWS * KVW];
__device__ float g_att[MROWS * E];

__device__ __nv_bfloat16 g_xhi[MROWS * E];
__device__ __nv_bfloat16 g_xlo[MROWS * E];
__device__ __nv_bfloat16 g_ahi[MROWS * E];
__device__ __nv_bfloat16 g_alo[MROWS * E];
__device__ __nv_bfloat16 g_wqt_hi[E * E];
__device__ __nv_bfloat16 g_wqt_lo[E * E];
__device__ __nv_bfloat16 g_wkt_hi[KVW * E];
__device__ __nv_bfloat16 g_wkt_lo[KVW * E];
__device__ __nv_bfloat16 g_wvt_hi[KVW * E];
__device__ __nv_bfloat16 g_wvt_lo[KVW * E];
__device__ __nv_bfloat16 g_wot_hi[E * E];
__device__ __nv_bfloat16 g_wot_lo[E * E];

// ---------------- helpers -------------------------------------------------
__device__ __forceinline__ uint32_t smem_u32(const void* p) {
    uint32_t a;
    asm("{ .reg .u64 t; cvta.to.shared.u64 t, %1; cvt.u32.u64 %0, t; }"
        : "=r"(a) : "l"(p));
    return a;
}
__device__ __forceinline__ void cp16(uint32_t dst, const void* src) {
    asm volatile("cp.async.cg.shared.global [%0], [%1], 16;"
                 :: "r"(dst), "l"(src));
}
#define CP_COMMIT() asm volatile("cp.async.commit_group;" ::: "memory")

#define MMA_BF16(acc, a, b)                                                  \
    asm volatile("mma.sync.aligned.m16n8k16.row.col.f32.bf16.bf16.f32 "      \
        "{%0,%1,%2,%3}, {%4,%5,%6,%7}, {%8,%9}, {%0,%1,%2,%3};"              \
        : "+f"((acc)[0]), "+f"((acc)[1]), "+f"((acc)[2]), "+f"((acc)[3])     \
        : "r"((a)[0]), "r"((a)[1]), "r"((a)[2]), "r"((a)[3]),                \
          "r"((b)[0]), "r"((b)[1]))

// ---------------- prep kernels -------------------------------------------
__global__ void split_fp32(const float* __restrict__ X,
                           __nv_bfloat16* __restrict__ hi,
                           __nv_bfloat16* __restrict__ lo, int n4)
{
    int i = blockIdx.x * blockDim.x + threadIdx.x;
    if (i >= n4) return;
    float4 v = ((const float4*)X)[i];
    __align__(8) __nv_bfloat16 h[4], l[4];
    float vv[4] = {v.x, v.y, v.z, v.w};
#pragma unroll
    for (int j = 0; j < 4; j++) {
        h[j] = __float2bfloat16(vv[j]);
        l[j] = __float2bfloat16(vv[j] - __bfloat162float(h[j]));
    }
    ((uint2*)hi)[i] = *(uint2*)h;
    ((uint2*)lo)[i] = *(uint2*)l;
}

__global__ void transpose_split(const float* __restrict__ W,
                                __nv_bfloat16* __restrict__ Thi,
                                __nv_bfloat16* __restrict__ Tlo,
                                int R, int C)
{
    __shared__ float tile[32][33];
    int c0 = blockIdx.x * 32, r0 = blockIdx.y * 32;
    int tx = threadIdx.x, ty = threadIdx.y;   // 32 x 8
#pragma unroll
    for (int i = 0; i < 32; i += 8)
        tile[ty + i][tx] = W[(size_t)(r0 + ty + i) * C + c0 + tx];
    __syncthreads();
#pragma unroll
    for (int i = 0; i < 32; i += 8) {
        float v = tile[tx][ty + i];
        __nv_bfloat16 h = __float2bfloat16(v);
        __nv_bfloat16 l = __float2bfloat16(v - __bfloat162float(h));
        size_t o = (size_t)(c0 + ty + i) * R + r0 + tx;
        Thi[o] = h; Tlo[o] = l;
    }
}

// ---------------- HMMA GEMM ----------------------------------------------
// C[M,N] = (Ahi+Alo)[M,K] * (Bhi+Blo)^T + bias   (B stored [N,K] row-major)
// CTA tile 128x128x32, 8 warps (2x4), warp tile 64x32 (4x4 m16n8k16),
// bf16 3-pass split into shared fp32 accumulators, cp.async double buffer.
#define SSTR        40                       // padded row stride, bf16 units
#define BUF_BYTES   (128 * SSTR * 2)         // 10240 B per operand buffer
#define STAGE_BYTES (4 * BUF_BYTES)          // 40960 B per stage
#define GEMM_SMEM   (2 * STAGE_BYTES)        // 81920 B

__global__ __launch_bounds__(256, 1)
void gemm_hmma(const __nv_bfloat16* __restrict__ Ahi,
               const __nv_bfloat16* __restrict__ Alo,
               const __nv_bfloat16* __restrict__ Bh0,
               const __nv_bfloat16* __restrict__ Bl0,
               const float* __restrict__ bias0, float* __restrict__ C0,
               const __nv_bfloat16* __restrict__ Bh1,
               const __nv_bfloat16* __restrict__ Bl1,
               const float* __restrict__ bias1, float* __restrict__ C1,
               int M, int N, int K)
{
    extern __shared__ __nv_bfloat16 smem[];
    const uint32_t sb = smem_u32(smem);

    const __nv_bfloat16* Bhi  = blockIdx.z ? Bh1   : Bh0;
    const __nv_bfloat16* Blo  = blockIdx.z ? Bl1   : Bl0;
    const float*         bias = blockIdx.z ? bias1 : bias0;
    float*               C    = blockIdx.z ? C1    : C0;

    const int tid  = threadIdx.x;
    const int wid  = tid >> 5;
    const int lane = tid & 31;
    const int wm   = wid >> 2;          // 0..1  (m offset *64)
    const int wn   = wid & 3;           // 0..3  (n offset *32)
    const int g    = lane >> 2;         // 0..7
    const int t4   = lane & 3;          // 0..3
    const int m0   = blockIdx.y * 128;
    const int n0   = blockIdx.x * 128;

    float acc[4][4][4];
#pragma unroll
    for (int i = 0; i < 4; i++)
#pragma unroll
        for (int j = 0; j < 4; j++)
#pragma unroll
            for (int r = 0; r < 4; r++) acc[i][j][r] = 0.f;

    // stage loader: 4 buffers x 512 16B-chunks; 8 cp.async per thread
    auto load_stage = [&](int st, int k0) {
        uint32_t base = sb + st * STAGE_BYTES;
#pragma unroll
        for (int half = 0; half < 2; half++) {
            int t   = tid + half * 256;
            int row = t >> 2;
            int ch  = t & 3;
            uint32_t doff = row * (SSTR * 2) + ch * 16;
            const size_t aoff = (size_t)(m0 + row) * K + k0 + ch * 8;
            const size_t boff = (size_t)(n0 + row) * K + k0 + ch * 8;
            cp16(base + 0 * BUF_BYTES + doff, Ahi + aoff);
            cp16(base + 1 * BUF_BYTES + doff, Alo + aoff);
            cp16(base + 2 * BUF_BYTES + doff, Bhi + boff);
            cp16(base + 3 * BUF_BYTES + doff, Blo + boff);
        }
    };

    const int NC = K / 32;
    load_stage(0, 0);
    CP_COMMIT();

    for (int cidx = 0; cidx < NC; ++cidx) {
        if (cidx + 1 < NC) {
            load_stage((cidx + 1) & 1, (cidx + 1) * 32);
            CP_COMMIT();
            asm volatile("cp.async.wait_group 1;" ::: "memory");
        } else {
            asm volatile("cp.async.wait_group 0;" ::: "memory");
        }
        __syncthreads();

        const __nv_bfloat16* sAh = smem + (cidx & 1) * (STAGE_BYTES / 2);
        const __nv_bfloat16* sAl = sAh + 128 * SSTR;
        const __nv_bfloat16* sBh = sAl + 128 * SSTR;
        const __nv_bfloat16* sBl = sBh + 128 * SSTR;

#pragma unroll
        for (int kk = 0; kk < 32; kk += 16) {
            const int c = kk + t4 * 2;
            uint32_t ah[4][4], al[4][4];
#pragma unroll
            for (int i = 0; i < 4; i++) {
                int r = wm * 64 + i * 16 + g;
                const uint32_t* p0h = (const uint32_t*)(sAh + r * SSTR + c);
                const uint32_t* p8h = (const uint32_t*)(sAh + (r + 8) * SSTR + c);
                ah[i][0] = p0h[0]; ah[i][1] = p8h[0];
                ah[i][2] = p0h[4]; ah[i][3] = p8h[4];
                const uint32_t* p0l = (const uint32_t*)(sAl + r * SSTR + c);
                const uint32_t* p8l = (const uint32_t*)(sAl + (r + 8) * SSTR + c);
                al[i][0] = p0l[0]; al[i][1] = p8l[0];
                al[i][2] = p0l[4]; al[i][3] = p8l[4];
            }
            uint32_t bh[4][2], bl[4][2];
#pragma unroll
            for (int j = 0; j < 4; j++) {
                int n = wn * 32 + j * 8 + g;
                const uint32_t* pbh = (const uint32_t*)(sBh + n * SSTR + c);
                const uint32_t* pbl = (const uint32_t*)(sBl + n * SSTR + c);
                bh[j][0] = pbh[0]; bh[j][1] = pbh[4];
                bl[j][0] = pbl[0]; bl[j][1] = pbl[4];
            }
#pragma unroll
            for (int i = 0; i < 4; i++)
#pragma unroll
                for (int j = 0; j < 4; j++) {
                    MMA_BF16(acc[i][j], ah[i], bh[j]);   // hi * hi
                    MMA_BF16(acc[i][j], ah[i], bl[j]);   // hi * lo
                    MMA_BF16(acc[i][j], al[i], bh[j]);   // lo * hi
                }
        }
        __syncthreads();
    }

    // epilogue
#pragma unroll
    for (int i = 0; i < 4; i++) {
        int row = m0 + wm * 64 + i * 16 + g;
#pragma unroll
        for (int j = 0; j < 4; j++) {
            int col = n0 + wn * 32 + j * 8 + t4 * 2;
            float b0 = bias[col], b1 = bias[col + 1];
            float2 o0 = make_float2(acc[i][j][0] + b0, acc[i][j][1] + b1);
            float2 o1 = make_float2(acc[i][j][2] + b0, acc[i][j][3] + b1);
            *(float2*)(C + (size_t)row * N + col)       = o0;
            *(float2*)(C + (size_t)(row + 8) * N + col) = o1;
        }
    }
}

// ---------------- RoPE (in-place, rotate-half, pos = (t%1024)+1) --------
__global__ void rope_kernel(float* __restrict__ q, int width, int npairs)
{
    int p = blockIdx.x * blockDim.x + threadIdx.x;
    if (p >= npairs) return;
    const int half = width >> 1;
    const int row  = p / half;
    const int rem  = p - row * half;
    const int head = rem >> 5;
    const int c    = rem & 31;
    const int base = row * width + head * HD + c;

    float x0 = q[base];
    float x1 = q[base + 32];
    float pos   = (float)((row & (TT - 1)) + 1);
    float theta = 1.0f / powf(10000.0f, (float)c * (1.0f / 32.0f));
    float ang   = pos * theta;
    float s, co;
    sincosf(ang, &s, &co);
    q[base]      = x0 * co - x1 * s;
    q[base + 32] = x1 * co + x0 * s;
}

// ---------------- Flash attention: 64x64 tiles, fp32 --------------------
#define ATTN_SMEM ((64 * 64 + 64 * 65 + 64 * 64) * 4)

__global__ __launch_bounds__(256)
void attn_kernel(const float* __restrict__ q, const float* __restrict__ k,
                 const float* __restrict__ v, float* __restrict__ o)
{
    extern __shared__ float sm[];
    float* Qs = sm;                 // [64][64]  Qs[d*64 + m]
    float* Ks = sm + 64 * 64;       // [64][65]  Ks[c*65 + d]  (later P)
    float* Vs = Ks + 64 * 65;       // [64][64]

    const int qb  = blockIdx.x;
    const int h   = blockIdx.y;
    const int bb  = blockIdx.z;
    const int kvh = h >> 2;
    const int tid = threadIdx.x;
    const int tx  = tid & 15;
    const int ty  = tid >> 4;
    const int r0  = ty << 2;
    const int c0  = tx << 2;
    const int qrow0 = bb * TT + qb * 64;

    for (int i = tid; i < 64 * 64; i += 256) {
        int m = i >> 6, d = i & 63;
        Qs[d * 64 + m] = q[(size_t)(qrow0 + m) * E + h * HD + d];
    }
    __syncthreads();

    float acc[4][4];
    float mr[4], lr[4];
#pragma unroll
    for (int i = 0; i < 4; i++) {
        mr[i] = -INFINITY; lr[i] = 0.f;
#pragma unroll
        for (int j = 0; j < 4; j++) acc[i][j] = 0.f;
    }

    for (int jb = 0; jb <= qb; ++jb) {
        const int krow0 = bb * TT + jb * 64;
        for (int i = tid; i < 64 * 64; i += 256) {
            int m = i >> 6, d = i & 63;
            size_t gidx = (size_t)(krow0 + m) * KVW + kvh * HD + d;
            Ks[m * 65 + d] = k[gidx];
            Vs[m * 64 + d] = v[gidx];
        }
        __syncthreads();

        float s[4][4];
#pragma unroll
        for (int i = 0; i < 4; i++)
#pragma unroll
            for (int j = 0; j < 4; j++) s[i][j] = 0.f;

#pragma unroll 16
        for (int d = 0; d < 64; ++d) {
            float4 qv = *(const float4*)(Qs + d * 64 + r0);
            float qa[4] = {qv.x, qv.y, qv.z, qv.w};
            float kb[4];
#pragma unroll
            for (int j = 0; j < 4; j++) kb[j] = Ks[(c0 + j) * 65 + d];
#pragma unroll
            for (int i = 0; i < 4; i++)
#pragma unroll
                for (int j = 0; j < 4; j++)
                    s[i][j] = fmaf(qa[i], kb[j], s[i][j]);
        }

        const bool diag = (jb == qb);
#pragma unroll
        for (int i = 0; i < 4; i++)
#pragma unroll
            for (int j = 0; j < 4; j++) {
                float val = s[i][j] * 0.125f;
                if (diag && (c0 + j) > (r0 + i)) val = -1e30f;
                s[i][j] = val;
            }

#pragma unroll
        for (int i = 0; i < 4; i++) {
            float rm = fmaxf(fmaxf(s[i][0], s[i][1]), fmaxf(s[i][2], s[i][3]));
#pragma unroll
            for (int off = 8; off; off >>= 1)
                rm = fmaxf(rm, __shfl_xor_sync(0xffffffffu, rm, off));
            float mnew  = fmaxf(mr[i], rm);
            float alpha = expf(mr[i] - mnew);
            float rs = 0.f;
#pragma unroll
            for (int j = 0; j < 4; j++) {
                s[i][j] = expf(s[i][j] - mnew);
                rs += s[i][j];
            }
#pragma unroll
            for (int off = 8; off; off >>= 1)
                rs += __shfl_xor_sync(0xffffffffu, rs, off);
            lr[i] = lr[i] * alpha + rs;
            mr[i] = mnew;
#pragma unroll
            for (int j = 0; j < 4; j++) acc[i][j] *= alpha;
        }

        __syncthreads();
#pragma unroll
        for (int i = 0; i < 4; i++)
#pragma unroll
            for (int j = 0; j < 4; j++)
                Ks[(r0 + i) * 65 + (c0 + j)] = s[i][j];
        __syncthreads();

#pragma unroll 8
        for (int kk = 0; kk < 64; ++kk) {
            float pa[4], vb[4];
#pragma unroll
            for (int i = 0; i < 4; i++) pa[i] = Ks[(r0 + i) * 65 + kk];
#pragma unroll
            for (int j = 0; j < 4; j++) vb[j] = Vs[kk * 64 + c0 + j];
#pragma unroll
            for (int i = 0; i < 4; i++)
#pragma unroll
                for (int j = 0; j < 4; j++)
                    acc[i][j] = fmaf(pa[i], vb[j], acc[i][j]);
        }
        __syncthreads();
    }

#pragma unroll
    for (int i = 0; i < 4; i++) {
        float inv = 1.0f / lr[i];
        size_t base = (size_t)(qrow0 + r0 + i) * E + h * HD + c0;
#pragma unroll
        for (int j = 0; j < 4; j++)
            o[base + j] = acc[i][j] * inv;
    }
}

// ---------------- launcher ----------------------------------------------
extern "C" void kernel_launch(void* const* d_in, const int* in_sizes, int n_in,
                              void* d_out, int out_size)
{
    const float* x  = (const float*)d_in[0];
    const float* wq = (const float*)d_in[1];
    const float* bq = (const float*)d_in[2];
    const float* wk = (const float*)d_in[3];
    const float* bk = (const float*)d_in[4];
    const float* wv = (const float*)d_in[5];
    const float* bv = (const float*)d_in[6];
    const float* wo = (const float*)d_in[7];
    const float* bo = (const float*)d_in[8];
    float* out = (float*)d_out;

    float *q, *k, *v, *att;
    __nv_bfloat16 *xhi, *xlo, *ahi, *alo;
    __nv_bfloat16 *wqh, *wql, *wkh, *wkl, *wvh, *wvl, *woh, *wol;
    cudaGetSymbolAddress((void**)&q,   g_q);
    cudaGetSymbolAddress((void**)&k,   g_k);
    cudaGetSymbolAddress((void**)&v,   g_v);
    cudaGetSymbolAddress((void**)&att, g_att);
    cudaGetSymbolAddress((void**)&xhi, g_xhi);
    cudaGetSymbolAddress((void**)&xlo, g_xlo);
    cudaGetSymbolAddress((void**)&ahi, g_ahi);
    cudaGetSymbolAddress((void**)&alo, g_alo);
    cudaGetSymbolAddress((void**)&wqh, g_wqt_hi);
    cudaGetSymbolAddress((void**)&wql, g_wqt_lo);
    cudaGetSymbolAddress((void**)&wkh, g_wkt_hi);
    cudaGetSymbolAddress((void**)&wkl, g_wkt_lo);
    cudaGetSymbolAddress((void**)&wvh, g_wvt_hi);
    cudaGetSymbolAddress((void**)&wvl, g_wvt_lo);
    cudaGetSymbolAddress((void**)&woh, g_wot_hi);
    cudaGetSymbolAddress((void**)&wol, g_wot_lo);

    cudaFuncSetAttribute(attn_kernel,
                         cudaFuncAttributeMaxDynamicSharedMemorySize, ATTN_SMEM);
    cudaFuncSetAttribute(gemm_hmma,
                         cudaFuncAttributeMaxDynamicSharedMemorySize, GEMM_SMEM);

    // ---- prep ----
    {
        int n4 = MROWS * E / 4;
        split_fp32<<<(n4 + 255) / 256, 256>>>(x, xhi, xlo, n4);
        transpose_split<<<dim3(E / 32,   E / 32), dim3(32, 8)>>>(wq, wqh, wql, E, E);
        transpose_split<<<dim3(KVW / 32, E / 32), dim3(32, 8)>>>(wk, wkh, wkl, E, KVW);
        transpose_split<<<dim3(KVW / 32, E / 32), dim3(32, 8)>>>(wv, wvh, wvl, E, KVW);
        transpose_split<<<dim3(E / 32,   E / 32), dim3(32, 8)>>>(wo, woh, wol, E, E);
    }

    // ---- projections on tensor pipe (HMMA) ----
    gemm_hmma<<<dim3(E / 128, MROWS / 128, 1), 256, GEMM_SMEM>>>(
        xhi, xlo, wqh, wql, bq, q, wqh, wql, bq, q, MROWS, E, E);
    gemm_hmma<<<dim3(KVW / 128, MROWS / 128, 2), 256, GEMM_SMEM>>>(
        xhi, xlo, wkh, wkl, bk, k, wvh, wvl, bv, v, MROWS, KVW, E);

    // ---- RoPE ----
    {
        int npq = MROWS * (E / 2);
        int npk = MROWS * (KVW / 2);
        rope_kernel<<<(npq + 255) / 256, 256>>>(q, E,   npq);
        rope_kernel<<<(npk + 255) / 256, 256>>>(k, KVW, npk);
    }

    // ---- attention (fp32 SIMT) ----
    attn_kernel<<<dim3(TT / 64, NQ, BATCH), 256, ATTN_SMEM>>>(q, k, v, att);

    // ---- output projection ----
    {
        int n4 = MROWS * E / 4;
        split_fp32<<<(n4 + 255) / 256, 256>>>(att, ahi, alo, n4);
    }
    gemm_hmma<<<dim3(E / 128, MROWS / 128, 1), 256, GEMM_SMEM>>>(
        ahi, alo, woh, wol, bo, out, woh, wol, bo, out, MROWS, E, E);
}

// round 17
// speedup vs baseline: 1.3144x; 1.3144x over previous
#include <cuda_runtime.h>
#include <cuda_bf16.h>
#include <math.h>
#include <stdint.h>

#define E      2048
#define TT     1024
#define BATCH  2
#define MROWS  (BATCH * TT)   // 2048
#define NKV    8
#define NQ     32
#define HD     64
#define KVW    (NKV * HD)     // 512

// ---------------- scratch (device globals; no allocations allowed) -------
__device__ float g_q[MROWS * E];
__device__ float g_k[MROWS * KVW];
__device__ float g_v[MROWS * KVW];

__device__ __nv_bfloat16 g_xhi[MROWS * E];
__device__ __nv_bfloat16 g_xlo[MROWS * E];
__device__ __nv_bfloat16 g_ahi[MROWS * E];
__device__ __nv_bfloat16 g_alo[MROWS * E];
__device__ __nv_bfloat16 g_qhi[MROWS * E];
__device__ __nv_bfloat16 g_qlo[MROWS * E];
__device__ __nv_bfloat16 g_khi[MROWS * KVW];
__device__ __nv_bfloat16 g_klo[MROWS * KVW];
__device__ __nv_bfloat16 g_vthi[MROWS * KVW];   // [b][kvh][d][t]
__device__ __nv_bfloat16 g_vtlo[MROWS * KVW];
__device__ __nv_bfloat16 g_wqt_hi[E * E];
__device__ __nv_bfloat16 g_wqt_lo[E * E];
__device__ __nv_bfloat16 g_wkt_hi[KVW * E];
__device__ __nv_bfloat16 g_wkt_lo[KVW * E];
__device__ __nv_bfloat16 g_wvt_hi[KVW * E];
__device__ __nv_bfloat16 g_wvt_lo[KVW * E];
__device__ __nv_bfloat16 g_wot_hi[E * E];
__device__ __nv_bfloat16 g_wot_lo[E * E];

// ---------------- helpers -------------------------------------------------
__device__ __forceinline__ uint32_t smem_u32(const void* p) {
    uint32_t a;
    asm("{ .reg .u64 t; cvta.to.shared.u64 t, %1; cvt.u32.u64 %0, t; }"
        : "=r"(a) : "l"(p));
    return a;
}
__device__ __forceinline__ void cp16(uint32_t dst, const void* src) {
    asm volatile("cp.async.cg.shared.global [%0], [%1], 16;"
                 :: "r"(dst), "l"(src));
}
#define CP_COMMIT() asm volatile("cp.async.commit_group;" ::: "memory")

#define MMA_BF16(acc, a, b)                                                  \
    asm volatile("mma.sync.aligned.m16n8k16.row.col.f32.bf16.bf16.f32 "      \
        "{%0,%1,%2,%3}, {%4,%5,%6,%7}, {%8,%9}, {%0,%1,%2,%3};"              \
        : "+f"((acc)[0]), "+f"((acc)[1]), "+f"((acc)[2]), "+f"((acc)[3])     \
        : "r"((a)[0]), "r"((a)[1]), "r"((a)[2]), "r"((a)[3]),                \
          "r"((b)[0]), "r"((b)[1]))

// split two fp32 into packed bf16x2 hi and lo
__device__ __forceinline__ void packsplit(float a, float b,
                                          uint32_t& hi, uint32_t& lo) {
    __nv_bfloat16 ha = __float2bfloat16(a);
    __nv_bfloat16 hb = __float2bfloat16(b);
    __nv_bfloat162 h2; h2.x = ha; h2.y = hb;
    hi = *(uint32_t*)&h2;
    __nv_bfloat162 l2 = __floats2bfloat162_rn(a - __bfloat162float(ha),
                                              b - __bfloat162float(hb));
    lo = *(uint32_t*)&l2;
}

// ---------------- prep kernels -------------------------------------------
__global__ void split_fp32(const float* __restrict__ X,
                           __nv_bfloat16* __restrict__ hi,
                           __nv_bfloat16* __restrict__ lo, int n4)
{
    int i = blockIdx.x * blockDim.x + threadIdx.x;
    if (i >= n4) return;
    float4 v = ((const float4*)X)[i];
    __align__(8) __nv_bfloat16 h[4], l[4];
    float vv[4] = {v.x, v.y, v.z, v.w};
#pragma unroll
    for (int j = 0; j < 4; j++) {
        h[j] = __float2bfloat16(vv[j]);
        l[j] = __float2bfloat16(vv[j] - __bfloat162float(h[j]));
    }
    ((uint2*)hi)[i] = *(uint2*)h;
    ((uint2*)lo)[i] = *(uint2*)l;
}

__global__ void transpose_split(const float* __restrict__ W,
                                __nv_bfloat16* __restrict__ Thi,
                                __nv_bfloat16* __restrict__ Tlo,
                                int R, int C)
{
    __shared__ float tile[32][33];
    int c0 = blockIdx.x * 32, r0 = blockIdx.y * 32;
    int tx = threadIdx.x, ty = threadIdx.y;   // 32 x 8
#pragma unroll
    for (int i = 0; i < 32; i += 8)
        tile[ty + i][tx] = W[(size_t)(r0 + ty + i) * C + c0 + tx];
    __syncthreads();
#pragma unroll
    for (int i = 0; i < 32; i += 8) {
        float v = tile[tx][ty + i];
        __nv_bfloat16 h = __float2bfloat16(v);
        __nv_bfloat16 l = __float2bfloat16(v - __bfloat162float(h));
        size_t o = (size_t)(c0 + ty + i) * R + r0 + tx;
        Thi[o] = h; Tlo[o] = l;
    }
}

// RoPE + hi/lo split in one pass (reads fp32, writes bf16 hi/lo)
__global__ void rope_split(const float* __restrict__ src,
                           __nv_bfloat16* __restrict__ hi,
                           __nv_bfloat16* __restrict__ lo,
                           int width, int npairs)
{
    int p = blockIdx.x * blockDim.x + threadIdx.x;
    if (p >= npairs) return;
    const int half = width >> 1;
    const int row  = p / half;
    const int rem  = p - row * half;
    const int head = rem >> 5;
    const int c    = rem & 31;
    const int base = row * width + head * HD + c;

    float x0 = src[base];
    float x1 = src[base + 32];
    float pos   = (float)((row & (TT - 1)) + 1);
    float theta = 1.0f / powf(10000.0f, (float)c * (1.0f / 32.0f));
    float ang   = pos * theta;
    float s, co;
    sincosf(ang, &s, &co);
    float y0 = x0 * co - x1 * s;
    float y1 = x1 * co + x0 * s;

    __nv_bfloat16 h0 = __float2bfloat16(y0);
    __nv_bfloat16 h1 = __float2bfloat16(y1);
    hi[base]      = h0;
    hi[base + 32] = h1;
    lo[base]      = __float2bfloat16(y0 - __bfloat162float(h0));
    lo[base + 32] = __float2bfloat16(y1 - __bfloat162float(h1));
}

// V fp32 [token][kvh*HD+d]  ->  bf16 hi/lo transposed [b][kvh][d][t]
__global__ void vt_split(const float* __restrict__ V,
                         __nv_bfloat16* __restrict__ Thi,
                         __nv_bfloat16* __restrict__ Tlo)
{
    __shared__ float tile[32][33];
    const int b   = blockIdx.z;
    const int kvh = blockIdx.y >> 1;
    const int d0  = (blockIdx.y & 1) * 32;
    const int t0  = blockIdx.x * 32;
    const int tx = threadIdx.x, ty = threadIdx.y;  // 32 x 8
#pragma unroll
    for (int i = 0; i < 32; i += 8)
        tile[ty + i][tx] = V[(size_t)(b * TT + t0 + ty + i) * KVW + kvh * HD + d0 + tx];
    __syncthreads();
#pragma unroll
    for (int i = 0; i < 32; i += 8) {
        float v = tile[tx][ty + i];                // V[t0+tx][d0+ty+i]
        __nv_bfloat16 h = __float2bfloat16(v);
        __nv_bfloat16 l = __float2bfloat16(v - __bfloat162float(h));
        size_t o = ((size_t)(b * NKV + kvh) * HD + d0 + ty + i) * TT + t0 + tx;
        Thi[o] = h; Tlo[o] = l;
    }
}

// ---------------- HMMA GEMM (unchanged from R16) --------------------------
#define SSTR        40
#define BUF_BYTES   (128 * SSTR * 2)
#define STAGE_BYTES (4 * BUF_BYTES)
#define GEMM_SMEM   (2 * STAGE_BYTES)

__global__ __launch_bounds__(256, 1)
void gemm_hmma(const __nv_bfloat16* __restrict__ Ahi,
               const __nv_bfloat16* __restrict__ Alo,
               const __nv_bfloat16* __restrict__ Bh0,
               const __nv_bfloat16* __restrict__ Bl0,
               const float* __restrict__ bias0, float* __restrict__ C0,
               const __nv_bfloat16* __restrict__ Bh1,
               const __nv_bfloat16* __restrict__ Bl1,
               const float* __restrict__ bias1, float* __restrict__ C1,
               int M, int N, int K)
{
    extern __shared__ __nv_bfloat16 smem[];
    const uint32_t sb = smem_u32(smem);

    const __nv_bfloat16* Bhi  = blockIdx.z ? Bh1   : Bh0;
    const __nv_bfloat16* Blo  = blockIdx.z ? Bl1   : Bl0;
    const float*         bias = blockIdx.z ? bias1 : bias0;
    float*               C    = blockIdx.z ? C1    : C0;

    const int tid  = threadIdx.x;
    const int wid  = tid >> 5;
    const int lane = tid & 31;
    const int wm   = wid >> 2;
    const int wn   = wid & 3;
    const int g    = lane >> 2;
    const int t4   = lane & 3;
    const int m0   = blockIdx.y * 128;
    const int n0   = blockIdx.x * 128;

    float acc[4][4][4];
#pragma unroll
    for (int i = 0; i < 4; i++)
#pragma unroll
        for (int j = 0; j < 4; j++)
#pragma unroll
            for (int r = 0; r < 4; r++) acc[i][j][r] = 0.f;

    auto load_stage = [&](int st, int k0) {
        uint32_t base = sb + st * STAGE_BYTES;
#pragma unroll
        for (int half = 0; half < 2; half++) {
            int t   = tid + half * 256;
            int row = t >> 2;
            int ch  = t & 3;
            uint32_t doff = row * (SSTR * 2) + ch * 16;
            const size_t aoff = (size_t)(m0 + row) * K + k0 + ch * 8;
            const size_t boff = (size_t)(n0 + row) * K + k0 + ch * 8;
            cp16(base + 0 * BUF_BYTES + doff, Ahi + aoff);
            cp16(base + 1 * BUF_BYTES + doff, Alo + aoff);
            cp16(base + 2 * BUF_BYTES + doff, Bhi + boff);
            cp16(base + 3 * BUF_BYTES + doff, Blo + boff);
        }
    };

    const int NC = K / 32;
    load_stage(0, 0);
    CP_COMMIT();

    for (int cidx = 0; cidx < NC; ++cidx) {
        if (cidx + 1 < NC) {
            load_stage((cidx + 1) & 1, (cidx + 1) * 32);
            CP_COMMIT();
            asm volatile("cp.async.wait_group 1;" ::: "memory");
        } else {
            asm volatile("cp.async.wait_group 0;" ::: "memory");
        }
        __syncthreads();

        const __nv_bfloat16* sAh = smem + (cidx & 1) * (STAGE_BYTES / 2);
        const __nv_bfloat16* sAl = sAh + 128 * SSTR;
        const __nv_bfloat16* sBh = sAl + 128 * SSTR;
        const __nv_bfloat16* sBl = sBh + 128 * SSTR;

#pragma unroll
        for (int kk = 0; kk < 32; kk += 16) {
            const int c = kk + t4 * 2;
            uint32_t ah[4][4], al[4][4];
#pragma unroll
            for (int i = 0; i < 4; i++) {
                int r = wm * 64 + i * 16 + g;
                const uint32_t* p0h = (const uint32_t*)(sAh + r * SSTR + c);
                const uint32_t* p8h = (const uint32_t*)(sAh + (r + 8) * SSTR + c);
                ah[i][0] = p0h[0]; ah[i][1] = p8h[0];
                ah[i][2] = p0h[4]; ah[i][3] = p8h[4];
                const uint32_t* p0l = (const uint32_t*)(sAl + r * SSTR + c);
                const uint32_t* p8l = (const uint32_t*)(sAl + (r + 8) * SSTR + c);
                al[i][0] = p0l[0]; al[i][1] = p8l[0];
                al[i][2] = p0l[4]; al[i][3] = p8l[4];
            }
            uint32_t bh[4][2], bl[4][2];
#pragma unroll
            for (int j = 0; j < 4; j++) {
                int n = wn * 32 + j * 8 + g;
                const uint32_t* pbh = (const uint32_t*)(sBh + n * SSTR + c);
                const uint32_t* pbl = (const uint32_t*)(sBl + n * SSTR + c);
                bh[j][0] = pbh[0]; bh[j][1] = pbh[4];
                bl[j][0] = pbl[0]; bl[j][1] = pbl[4];
            }
#pragma unroll
            for (int i = 0; i < 4; i++)
#pragma unroll
                for (int j = 0; j < 4; j++) {
                    MMA_BF16(acc[i][j], ah[i], bh[j]);
                    MMA_BF16(acc[i][j], ah[i], bl[j]);
                    MMA_BF16(acc[i][j], al[i], bh[j]);
                }
        }
        __syncthreads();
    }

#pragma unroll
    for (int i = 0; i < 4; i++) {
        int row = m0 + wm * 64 + i * 16 + g;
#pragma unroll
        for (int j = 0; j < 4; j++) {
            int col = n0 + wn * 32 + j * 8 + t4 * 2;
            float b0 = bias[col], b1 = bias[col + 1];
            float2 o0 = make_float2(acc[i][j][0] + b0, acc[i][j][1] + b1);
            float2 o1 = make_float2(acc[i][j][2] + b0, acc[i][j][3] + b1);
            *(float2*)(C + (size_t)row * N + col)       = o0;
            *(float2*)(C + (size_t)(row + 8) * N + col) = o1;
        }
    }
}

// ---------------- HMMA flash attention ------------------------------------
// CTA: 128 q-rows x (64-wide K tiles). 8 warps, warp = m16 row slab spanning
// full n=64. S = QK^T via 3-pass hi/lo bf16 MMA; P kept in registers,
// converted to bf16 hi/lo A-fragments; PV via 3-pass MMA with transposed V.
#define ASTR       72                       // padded row stride (halves)
#define ABUF       (64 * ASTR)              // halves per buffer
#define ASTAGE_H   (4 * ABUF)               // halves per stage
#define ATTN_SMEM  (2 * ASTAGE_H * 2)       // bytes = 73728

__global__ __launch_bounds__(256, 2)
void attn_hmma(const __nv_bfloat16* __restrict__ qhi,
               const __nv_bfloat16* __restrict__ qlo,
               const __nv_bfloat16* __restrict__ khi,
               const __nv_bfloat16* __restrict__ klo,
               const __nv_bfloat16* __restrict__ vthi,
               const __nv_bfloat16* __restrict__ vtlo,
               __nv_bfloat16* __restrict__ ohi,
               __nv_bfloat16* __restrict__ olo)
{
    extern __shared__ __nv_bfloat16 smem[];
    const uint32_t sb = smem_u32(smem);

    const int qb  = blockIdx.x;      // 0..7 (128-row q blocks)
    const int h   = blockIdx.y;      // 0..31
    const int bb  = blockIdx.z;      // 0..1
    const int kvh = h >> 2;
    const int tid = threadIdx.x;
    const int wid = tid >> 5;        // warp = m16 slab index 0..7
    const int lane = tid & 31;
    const int g   = lane >> 2;
    const int t4  = lane & 3;
    const int qrow0 = bb * TT + qb * 128;
    const int rbase = qb * 128 + wid * 16;     // local (in-sequence) row base
    const int r0l = rbase + g;
    const int r1l = r0l + 8;
    const int nkt = 2 * qb + 2;

    auto load_stage = [&](int st, int kt) {
        uint32_t base = sb + st * ASTAGE_H * 2;
        const int krow0 = bb * TT + kt * 64;
#pragma unroll
        for (int half = 0; half < 2; half++) {
            int c   = tid + half * 256;          // 0..511
            int row = c >> 3;
            int ch  = c & 7;
            uint32_t doff = row * (ASTR * 2) + ch * 16;
            const size_t koff = (size_t)(krow0 + row) * KVW + kvh * HD + ch * 8;
            const size_t voff = ((size_t)(bb * NKV + kvh) * HD + row) * TT + kt * 64 + ch * 8;
            cp16(base + 0 * ABUF * 2 + doff, khi  + koff);
            cp16(base + 1 * ABUF * 2 + doff, klo  + koff);
            cp16(base + 2 * ABUF * 2 + doff, vthi + voff);
            cp16(base + 3 * ABUF * 2 + doff, vtlo + voff);
        }
    };

    load_stage(0, 0);
    CP_COMMIT();

    // Q fragments (held in registers for the whole kernel)
    uint32_t qh[4][4], ql[4][4];
    {
        const __nv_bfloat16* qr0h = qhi + (size_t)(qrow0 + wid * 16 + g) * E + h * HD;
        const __nv_bfloat16* qr8h = qr0h + 8 * (size_t)E;
        const __nv_bfloat16* qr0l = qlo + (size_t)(qrow0 + wid * 16 + g) * E + h * HD;
        const __nv_bfloat16* qr8l = qr0l + 8 * (size_t)E;
#pragma unroll
        for (int ks = 0; ks < 4; ks++) {
            int c = ks * 16 + 2 * t4;
            qh[ks][0] = *(const uint32_t*)(qr0h + c);
            qh[ks][1] = *(const uint32_t*)(qr8h + c);
            qh[ks][2] = *(const uint32_t*)(qr0h + c + 8);
            qh[ks][3] = *(const uint32_t*)(qr8h + c + 8);
            ql[ks][0] = *(const uint32_t*)(qr0l + c);
            ql[ks][1] = *(const uint32_t*)(qr8l + c);
            ql[ks][2] = *(const uint32_t*)(qr0l + c + 8);
            ql[ks][3] = *(const uint32_t*)(qr8l + c + 8);
        }
    }

    float o[8][4];
#pragma unroll
    for (int nt = 0; nt < 8; nt++)
#pragma unroll
        for (int c = 0; c < 4; c++) o[nt][c] = 0.f;
    float mr0 = -INFINITY, mr1 = -INFINITY, lr0 = 0.f, lr1 = 0.f;

    for (int kt = 0; kt < nkt; ++kt) {
        if (kt + 1 < nkt) {
            load_stage((kt + 1) & 1, kt + 1);
            CP_COMMIT();
            asm volatile("cp.async.wait_group 1;" ::: "memory");
        } else {
            asm volatile("cp.async.wait_group 0;" ::: "memory");
        }
        __syncthreads();

        if (kt * 64 <= rbase + 15) {             // warp not fully masked
            const __nv_bfloat16* sKh = smem + (kt & 1) * ASTAGE_H;
            const __nv_bfloat16* sKl = sKh + ABUF;
            const __nv_bfloat16* sVh = sKl + ABUF;
            const __nv_bfloat16* sVl = sVh + ABUF;

            // ---- S = Q K^T (3-pass hi/lo) ----
            float s[8][4];
#pragma unroll
            for (int nt = 0; nt < 8; nt++)
#pragma unroll
                for (int c = 0; c < 4; c++) s[nt][c] = 0.f;

#pragma unroll
            for (int ks = 0; ks < 4; ks++) {
#pragma unroll
                for (int nt = 0; nt < 8; nt++) {
                    const uint32_t* pbh = (const uint32_t*)(sKh + (nt * 8 + g) * ASTR + ks * 16 + 2 * t4);
                    const uint32_t* pbl = (const uint32_t*)(sKl + (nt * 8 + g) * ASTR + ks * 16 + 2 * t4);
                    uint32_t bh[2] = {pbh[0], pbh[4]};
                    uint32_t bl[2] = {pbl[0], pbl[4]};
                    MMA_BF16(s[nt], qh[ks], bh);
                    MMA_BF16(s[nt], qh[ks], bl);
                    MMA_BF16(s[nt], ql[ks], bh);
                }
            }

            // ---- scale + causal mask ----
            const bool needmask = (kt * 64 + 63 > r0l);
#pragma unroll
            for (int nt = 0; nt < 8; nt++) {
                int cb = kt * 64 + nt * 8 + 2 * t4;
                s[nt][0] *= 0.125f; s[nt][1] *= 0.125f;
                s[nt][2] *= 0.125f; s[nt][3] *= 0.125f;
                if (needmask) {
                    if (cb     > r0l) s[nt][0] = -1e30f;
                    if (cb + 1 > r0l) s[nt][1] = -1e30f;
                    if (cb     > r1l) s[nt][2] = -1e30f;
                    if (cb + 1 > r1l) s[nt][3] = -1e30f;
                }
            }

            // ---- online softmax (rows quad-local) ----
            float vm0 = -INFINITY, vm1 = -INFINITY;
#pragma unroll
            for (int nt = 0; nt < 8; nt++) {
                vm0 = fmaxf(vm0, fmaxf(s[nt][0], s[nt][1]));
                vm1 = fmaxf(vm1, fmaxf(s[nt][2], s[nt][3]));
            }
            vm0 = fmaxf(vm0, __shfl_xor_sync(0xffffffffu, vm0, 1));
            vm0 = fmaxf(vm0, __shfl_xor_sync(0xffffffffu, vm0, 2));
            vm1 = fmaxf(vm1, __shfl_xor_sync(0xffffffffu, vm1, 1));
            vm1 = fmaxf(vm1, __shfl_xor_sync(0xffffffffu, vm1, 2));
            float mn0 = fmaxf(mr0, vm0), mn1 = fmaxf(mr1, vm1);
            float a0 = __expf(mr0 - mn0), a1 = __expf(mr1 - mn1);
            float sum0 = 0.f, sum1 = 0.f;
#pragma unroll
            for (int nt = 0; nt < 8; nt++) {
                s[nt][0] = __expf(s[nt][0] - mn0); sum0 += s[nt][0];
                s[nt][1] = __expf(s[nt][1] - mn0); sum0 += s[nt][1];
                s[nt][2] = __expf(s[nt][2] - mn1); sum1 += s[nt][2];
                s[nt][3] = __expf(s[nt][3] - mn1); sum1 += s[nt][3];
            }
            sum0 += __shfl_xor_sync(0xffffffffu, sum0, 1);
            sum0 += __shfl_xor_sync(0xffffffffu, sum0, 2);
            sum1 += __shfl_xor_sync(0xffffffffu, sum1, 1);
            sum1 += __shfl_xor_sync(0xffffffffu, sum1, 2);
            lr0 = lr0 * a0 + sum0;
            lr1 = lr1 * a1 + sum1;
            mr0 = mn0; mr1 = mn1;
#pragma unroll
            for (int nt = 0; nt < 8; nt++) {
                o[nt][0] *= a0; o[nt][1] *= a0;
                o[nt][2] *= a1; o[nt][3] *= a1;
            }

            // ---- O += P V (P in registers, 3-pass hi/lo) ----
#pragma unroll
            for (int ks = 0; ks < 4; ks++) {
                uint32_t ph[4], pl[4];
                packsplit(s[2*ks][0],   s[2*ks][1],   ph[0], pl[0]);
                packsplit(s[2*ks][2],   s[2*ks][3],   ph[1], pl[1]);
                packsplit(s[2*ks+1][0], s[2*ks+1][1], ph[2], pl[2]);
                packsplit(s[2*ks+1][2], s[2*ks+1][3], ph[3], pl[3]);
#pragma unroll
                for (int nt = 0; nt < 8; nt++) {
                    const uint32_t* pvh = (const uint32_t*)(sVh + (nt * 8 + g) * ASTR + ks * 16 + 2 * t4);
                    const uint32_t* pvl = (const uint32_t*)(sVl + (nt * 8 + g) * ASTR + ks * 16 + 2 * t4);
                    uint32_t bh[2] = {pvh[0], pvh[4]};
                    uint32_t bl[2] = {pvl[0], pvl[4]};
                    MMA_BF16(o[nt], ph, bh);
                    MMA_BF16(o[nt], ph, bl);
                    MMA_BF16(o[nt], pl, bh);
                }
            }
        }
        __syncthreads();
    }

    // ---- epilogue: normalize, split to bf16 hi/lo, store ----
    const float inv0 = 1.0f / lr0, inv1 = 1.0f / lr1;
    const size_t ro0 = (size_t)(qrow0 + wid * 16 + g) * E + h * HD;
    const size_t ro8 = ro0 + 8 * (size_t)E;
#pragma unroll
    for (int nt = 0; nt < 8; nt++) {
        int col = nt * 8 + 2 * t4;
        uint32_t hh, ll;
        packsplit(o[nt][0] * inv0, o[nt][1] * inv0, hh, ll);
        *(uint32_t*)(ohi + ro0 + col) = hh;
        *(uint32_t*)(olo + ro0 + col) = ll;
        packsplit(o[nt][2] * inv1, o[nt][3] * inv1, hh, ll);
        *(uint32_t*)(ohi + ro8 + col) = hh;
        *(uint32_t*)(olo + ro8 + col) = ll;
    }
}

// ---------------- launcher ----------------------------------------------
extern "C" void kernel_launch(void* const* d_in, const int* in_sizes, int n_in,
                              void* d_out, int out_size)
{
    const float* x  = (const float*)d_in[0];
    const float* wq = (const float*)d_in[1];
    const float* bq = (const float*)d_in[2];
    const float* wk = (const float*)d_in[3];
    const float* bk = (const float*)d_in[4];
    const float* wv = (const float*)d_in[5];
    const float* bv = (const float*)d_in[6];
    const float* wo = (const float*)d_in[7];
    const float* bo = (const float*)d_in[8];
    float* out = (float*)d_out;

    float *q, *k, *v;
    __nv_bfloat16 *xhi, *xlo, *ahi, *alo;
    __nv_bfloat16 *qhi, *qlo, *khi, *klo, *vthi, *vtlo;
    __nv_bfloat16 *wqh, *wql, *wkh, *wkl, *wvh, *wvl, *woh, *wol;
    cudaGetSymbolAddress((void**)&q,    g_q);
    cudaGetSymbolAddress((void**)&k,    g_k);
    cudaGetSymbolAddress((void**)&v,    g_v);
    cudaGetSymbolAddress((void**)&xhi,  g_xhi);
    cudaGetSymbolAddress((void**)&xlo,  g_xlo);
    cudaGetSymbolAddress((void**)&ahi,  g_ahi);
    cudaGetSymbolAddress((void**)&alo,  g_alo);
    cudaGetSymbolAddress((void**)&qhi,  g_qhi);
    cudaGetSymbolAddress((void**)&qlo,  g_qlo);
    cudaGetSymbolAddress((void**)&khi,  g_khi);
    cudaGetSymbolAddress((void**)&klo,  g_klo);
    cudaGetSymbolAddress((void**)&vthi, g_vthi);
    cudaGetSymbolAddress((void**)&vtlo, g_vtlo);
    cudaGetSymbolAddress((void**)&wqh,  g_wqt_hi);
    cudaGetSymbolAddress((void**)&wql,  g_wqt_lo);
    cudaGetSymbolAddress((void**)&wkh,  g_wkt_hi);
    cudaGetSymbolAddress((void**)&wkl,  g_wkt_lo);
    cudaGetSymbolAddress((void**)&wvh,  g_wvt_hi);
    cudaGetSymbolAddress((void**)&wvl,  g_wvt_lo);
    cudaGetSymbolAddress((void**)&woh,  g_wot_hi);
    cudaGetSymbolAddress((void**)&wol,  g_wot_lo);

    cudaFuncSetAttribute(gemm_hmma,
                         cudaFuncAttributeMaxDynamicSharedMemorySize, GEMM_SMEM);
    cudaFuncSetAttribute(attn_hmma,
                         cudaFuncAttributeMaxDynamicSharedMemorySize, ATTN_SMEM);

    // ---- prep ----
    {
        int n4 = MROWS * E / 4;
        split_fp32<<<(n4 + 255) / 256, 256>>>(x, xhi, xlo, n4);
        transpose_split<<<dim3(E / 32,   E / 32), dim3(32, 8)>>>(wq, wqh, wql, E, E);
        transpose_split<<<dim3(KVW / 32, E / 32), dim3(32, 8)>>>(wk, wkh, wkl, E, KVW);
        transpose_split<<<dim3(KVW / 32, E / 32), dim3(32, 8)>>>(wv, wvh, wvl, E, KVW);
        transpose_split<<<dim3(E / 32,   E / 32), dim3(32, 8)>>>(wo, woh, wol, E, E);
    }

    // ---- projections (HMMA) ----
    gemm_hmma<<<dim3(E / 128, MROWS / 128, 1), 256, GEMM_SMEM>>>(
        xhi, xlo, wqh, wql, bq, q, wqh, wql, bq, q, MROWS, E, E);
    gemm_hmma<<<dim3(KVW / 128, MROWS / 128, 2), 256, GEMM_SMEM>>>(
        xhi, xlo, wkh, wkl, bk, k, wvh, wvl, bv, v, MROWS, KVW, E);

    // ---- RoPE + split to bf16 hi/lo; V transpose+split ----
    {
        int npq = MROWS * (E / 2);
        int npk = MROWS * (KVW / 2);
        rope_split<<<(npq + 255) / 256, 256>>>(q, qhi, qlo, E,   npq);
        rope_split<<<(npk + 255) / 256, 256>>>(k, khi, klo, KVW, npk);
        vt_split<<<dim3(TT / 32, NKV * 2, BATCH), dim3(32, 8)>>>(v, vthi, vtlo);
    }

    // ---- attention (HMMA, 3-pass hi/lo) ----
    attn_hmma<<<dim3(TT / 128, NQ, BATCH), 256, ATTN_SMEM>>>(
        qhi, qlo, khi, klo, vthi, vtlo, ahi, alo);

    // ---- output projection ----
    gemm_hmma<<<dim3(E / 128, MROWS / 128, 1), 256, GEMM_SMEM>>>(
        ahi, alo, woh, wol, bo, out, woh, wol, bo, out, MROWS, E, E);
}